// round 1
// baseline (speedup 1.0000x reference)
#include <cuda_runtime.h>
#include <cstdint>
#include <cstddef>

// ---------------------------------------------------------------------------
// Critic_Mix fused kernel (round 0): tf32 mma.sync, fully fused 2-head MLP mix.
//
// Shapes: B=262144, D_IN=128 (x 96 + u 32), H1=128, H2=64, K=4 teachers.
// Per CTA: BLOCK_M=64 batch rows, all 5 activation streams resident in SMEM.
// Numerics: tf32 (cvt.rna) operands, fp32 accumulate -> rel err ~= 5e-4.
// ---------------------------------------------------------------------------

#define BM       64
#define THREADS  256
#define BATCH    262144

// Swizzled SMEM addressing (stride 128 floats, XOR on bits[2:5) by row&7):
// conflict-free for both mma A/B fragment loads and epilogue stores.
#define SW(row, k) (((row) * 128) + ((k) ^ (((row) & 7) << 2)))

// floats: 5 act buffers (64x128) + weight buffer (128x128) + bias (128)
#define SMEM_ACT_STRIDE (64 * 128)
#define SMEM_W_OFF      (5 * SMEM_ACT_STRIDE)
#define SMEM_BIAS_OFF   (SMEM_W_OFF + 128 * 128)
#define SMEM_FLOATS     (SMEM_BIAS_OFF + 128)
#define SMEM_BYTES      (SMEM_FLOATS * 4)   // 229,888 B <= 232,448 B limit

struct Params {
    const float* x;        // [B, 96]
    const float* u;        // [B, 32]
    const float* mixf;     // [1]
    const float* P;        // [4]
    const float* W[2][3];  // main weights, layers 0..2, per head
    const float* Bb[2][3]; // main biases
    const float* W4[2];    // [64]
    const float* b4[2];    // [1]
    const float* tW[2][3]; // teacher weights [4, O, 128]
    const float* tb[2][3]; // teacher biases  [4, O]
    float*       out;      // [2*B]
};

__device__ __forceinline__ float to_tf32(float x) {
    asm("cvt.rna.tf32.f32 %0, %0;" : "+f"(x));
    return x;
}

// Load one stream's weight [O,128] fp32 row-major -> swizzled SMEM (tf32-rounded)
template <int O>
__device__ __forceinline__ void load_weight(const float* __restrict__ W,
                                            const float* __restrict__ bias,
                                            float* sW, float* sBias, int tid) {
    constexpr int NV = O * 32;  // number of float4
    #pragma unroll
    for (int i = tid; i < NV; i += THREADS) {
        int n = i >> 5;
        int q = (i & 31) * 4;
        float4 v = *reinterpret_cast<const float4*>(W + (size_t)n * 128 + q);
        v.x = to_tf32(v.x); v.y = to_tf32(v.y);
        v.z = to_tf32(v.z); v.w = to_tf32(v.w);
        // swizzle flips bits[2:5) only -> 16B-aligned vector store stays valid
        *reinterpret_cast<float4*>(sW + SW(n, q)) = v;
    }
    if (tid < O) sBias[tid] = bias[tid];
}

// One stream: weight load + [64,128]x[128,O] tf32 GEMM + mix/relu epilogue.
// mix[][][] persists across the 5 streams of a layer (same tile ownership).
template <int O>
__device__ __forceinline__ void process_stream(
    const float* __restrict__ gW, const float* __restrict__ gB,
    const float* sIn, float* sOut, float* sWbuf, float* sBias,
    float mix[2][4][4], float scale, bool is_main, int tid) {

    __syncthreads();                       // prior GEMM done with sWbuf
    load_weight<O>(gW, gB, sWbuf, sBias, tid);
    __syncthreads();                       // weights visible

    const int lane = tid & 31;
    const int wid  = tid >> 5;
    constexpr int MT = (O == 128) ? 2 : 1; // m16 tiles per warp
    int wm, wn;
    if (O == 128) { wm = wid & 1; wn = wid >> 1; }  // 2 x 4 warp grid
    else          { wm = wid & 3; wn = wid >> 2; }  // 4 x 2 warp grid
    const int mbase = wm * (MT * 16);
    const int nbase = wn * 32;
    const int lq = lane >> 2;   // group id
    const int lr = lane & 3;    // thread-in-group

    float acc[MT][4][4];
    #pragma unroll
    for (int mt = 0; mt < MT; mt++)
        #pragma unroll
        for (int nt = 0; nt < 4; nt++)
            #pragma unroll
            for (int c = 0; c < 4; c++) acc[mt][nt][c] = 0.f;

    #pragma unroll
    for (int k0 = 0; k0 < 128; k0 += 8) {
        uint32_t a[MT][4], b[4][2];
        #pragma unroll
        for (int mt = 0; mt < MT; mt++) {
            const int r0 = mbase + mt * 16 + lq;
            const int kc = k0 + lr;
            a[mt][0] = __float_as_uint(sIn[SW(r0,     kc)]);
            a[mt][1] = __float_as_uint(sIn[SW(r0 + 8, kc)]);
            a[mt][2] = __float_as_uint(sIn[SW(r0,     kc + 4)]);
            a[mt][3] = __float_as_uint(sIn[SW(r0 + 8, kc + 4)]);
        }
        #pragma unroll
        for (int nt = 0; nt < 4; nt++) {
            const int n = nbase + nt * 8 + lq;
            b[nt][0] = __float_as_uint(sWbuf[SW(n, k0 + lr)]);
            b[nt][1] = __float_as_uint(sWbuf[SW(n, k0 + lr + 4)]);
        }
        #pragma unroll
        for (int mt = 0; mt < MT; mt++)
            #pragma unroll
            for (int nt = 0; nt < 4; nt++) {
                asm volatile(
                    "mma.sync.aligned.m16n8k8.row.col.f32.tf32.tf32.f32 "
                    "{%0,%1,%2,%3}, {%4,%5,%6,%7}, {%8,%9}, {%0,%1,%2,%3};"
                    : "+f"(acc[mt][nt][0]), "+f"(acc[mt][nt][1]),
                      "+f"(acc[mt][nt][2]), "+f"(acc[mt][nt][3])
                    : "r"(a[mt][0]), "r"(a[mt][1]), "r"(a[mt][2]), "r"(a[mt][3]),
                      "r"(b[nt][0]), "r"(b[nt][1]));
            }
    }

    __syncthreads();   // every warp done reading sIn -> safe to overwrite

    #pragma unroll
    for (int mt = 0; mt < MT; mt++)
        #pragma unroll
        for (int nt = 0; nt < 4; nt++)
            #pragma unroll
            for (int c = 0; c < 4; c++) {
                const int row = mbase + nt * 0 + mt * 16 + lq + ((c >> 1) << 3);
                const int col = nbase + nt * 8 + lr * 2 + (c & 1);
                const float val = acc[mt][nt][c] + sBias[col];
                float o;
                if (!is_main) {           // teacher: accumulate mix, pass relu(pre)
                    mix[mt][nt][c] += scale * val;
                    o = val;
                } else {                  // main: (1-m)*val + m*sum(P_k * ht_k)
                    o = fmaf(scale, val, mix[mt][nt][c]);
                }
                sOut[SW(row, col)] = to_tf32(fmaxf(o, 0.f));
            }
}

__global__ void __launch_bounds__(THREADS)
critic_mix_kernel(Params p) {
    extern __shared__ float smem[];
    float* sAct  = smem;                    // 5 buffers of 64x128
    float* sWbuf = smem + SMEM_W_OFF;
    float* sBias = smem + SMEM_BIAS_OFF;

    const int tid  = threadIdx.x;
    const int row0 = blockIdx.x * BM;

    const float m = __ldg(p.mixf);
    float Pk[4];
    #pragma unroll
    for (int k = 0; k < 4; k++) Pk[k] = __ldg(p.P + k);
    const float inv_m = 1.0f - m;

    for (int h = 0; h < 2; h++) {
        // ---- load xu tile into buffer 4 (main stream / shared L0 input) ----
        {
            float* dst = sAct + 4 * SMEM_ACT_STRIDE;
            #pragma unroll
            for (int i = tid; i < 64 * 32; i += THREADS) {
                const int r = i >> 5;
                const int q = i & 31;           // float4 index within 128-wide row
                float4 v;
                if (q < 24)
                    v = *reinterpret_cast<const float4*>(
                        p.x + (size_t)(row0 + r) * 96 + q * 4);
                else
                    v = *reinterpret_cast<const float4*>(
                        p.u + (size_t)(row0 + r) * 32 + (q - 24) * 4);
                v.x = to_tf32(v.x); v.y = to_tf32(v.y);
                v.z = to_tf32(v.z); v.w = to_tf32(v.w);
                *reinterpret_cast<float4*>(dst + SW(r, q * 4)) = v;
            }
        }
        __syncthreads();

        float mix[2][4][4];
        #pragma unroll
        for (int L = 0; L < 3; L++) {
            #pragma unroll
            for (int mt = 0; mt < 2; mt++)
                #pragma unroll
                for (int nt = 0; nt < 4; nt++)
                    #pragma unroll
                    for (int c = 0; c < 4; c++) mix[mt][nt][c] = 0.f;

            const int O = (L == 2) ? 64 : 128;
            for (int s = 0; s < 5; s++) {
                const bool  is_main = (s == 4);
                const float scale   = is_main ? inv_m : (m * Pk[s]);
                const float* gW = is_main ? p.W[h][L]
                                          : p.tW[h][L] + (size_t)s * O * 128;
                const float* gB = is_main ? p.Bb[h][L] : p.tb[h][L] + s * O;
                const float* sIn  = sAct + ((L == 0) ? 4 : s) * SMEM_ACT_STRIDE;
                float*       sOut = sAct + ((s < 4) ? s : 4) * SMEM_ACT_STRIDE;

                if (O == 128)
                    process_stream<128>(gW, gB, sIn, sOut, sWbuf, sBias,
                                        mix, scale, is_main, tid);
                else
                    process_stream<64>(gW, gB, sIn, sOut, sWbuf, sBias,
                                       mix, scale, is_main, tid);
            }
        }

        __syncthreads();
        // ---- final layer: out = h3 @ W4^T + b4 (fp32 scalar, N=1) ----
        if (tid < 64) {
            const float* hbuf = sAct + 4 * SMEM_ACT_STRIDE;
            const int r = tid;
            float sum = __ldg(p.b4[h]);
            const float* W4 = p.W4[h];
            #pragma unroll
            for (int j = 0; j < 64; j++)
                sum = fmaf(hbuf[SW(r, j)], __ldg(W4 + j), sum);
            p.out[(size_t)h * BATCH + row0 + r] = sum;
        }
        __syncthreads();   // buffers free before head 2 reloads xu
    }
}

extern "C" void kernel_launch(void* const* d_in, const int* in_sizes, int n_in,
                              void* d_out, int out_size) {
    (void)in_sizes; (void)n_in; (void)out_size;
    Params p;
    p.x    = (const float*)d_in[0];
    p.u    = (const float*)d_in[1];
    p.mixf = (const float*)d_in[2];
    p.P    = (const float*)d_in[3];
    for (int h = 0; h < 2; h++) {
        const int base = 4 + h * 8;     // W1 b1 W2 b2 W3 b3 W4 b4 (then W5..b8)
        p.W[h][0]  = (const float*)d_in[base + 0];
        p.Bb[h][0] = (const float*)d_in[base + 1];
        p.W[h][1]  = (const float*)d_in[base + 2];
        p.Bb[h][1] = (const float*)d_in[base + 3];
        p.W[h][2]  = (const float*)d_in[base + 4];
        p.Bb[h][2] = (const float*)d_in[base + 5];
        p.W4[h]    = (const float*)d_in[base + 6];
        p.b4[h]    = (const float*)d_in[base + 7];
        const int tbase = 20 + h * 6;   // tW1 tb1 tW2 tb2 tW3 tb3 (then t5..t7)
        p.tW[h][0] = (const float*)d_in[tbase + 0];
        p.tb[h][0] = (const float*)d_in[tbase + 1];
        p.tW[h][1] = (const float*)d_in[tbase + 2];
        p.tb[h][1] = (const float*)d_in[tbase + 3];
        p.tW[h][2] = (const float*)d_in[tbase + 4];
        p.tb[h][2] = (const float*)d_in[tbase + 5];
    }
    p.out = (float*)d_out;

    cudaFuncSetAttribute(critic_mix_kernel,
                         cudaFuncAttributeMaxDynamicSharedMemorySize, SMEM_BYTES);
    critic_mix_kernel<<<BATCH / BM, THREADS, SMEM_BYTES>>>(p);
}

// round 4
// speedup vs baseline: 1.4674x; 1.4674x over previous
#include <cuda_runtime.h>
#include <cstdint>
#include <cstddef>

// ---------------------------------------------------------------------------
// Critic_Mix fused kernel (round 3): mma.sync tf32 + ldmatrix.x4 fragments +
// preprocessed (rounded/swizzled/padded) weight images pulled via cp.async.
// R3 fix: double-buffered bias slots — kills the cp.async-vs-epilogue race
// that broke R2 (weights were already race-free via wait+syncthreads).
// ---------------------------------------------------------------------------

#define THREADS   256
#define BM        64
#define BATCH     262144
#define NBLK      (BATCH / BM)

// SMEM (bytes): 5 act buffers (64x128 f32) | weight buffer 128x128 f32 | bias x2
#define ACT_B      32768
#define WBUF_OFF   (5 * ACT_B)          // 163840
#define BIAS_OFF   (WBUF_OFF + 65536)   // 229376
#define SMEM_BYTES (BIAS_OFF + 1024)    // 230400 <= 232448
#define BIAS_F     (BIAS_OFF / 4)       // float index of bias slot 0

// Swizzle: float index = row*128 + (k ^ ((row&7)<<2))  (R0-proven)
#define SWF(row, k) (((row) * 128) + ((k) ^ (((row) & 7) << 2)))

// Preprocessed weight images: 30 streams x [128 rows x 128 k] f32, swizzled,
// tf32-rounded, zero-padded (O=64 rows 64..127 = 0). Plus padded biases.
__device__ float g_wimg[30 * 16384];
__device__ float g_bimg[30 * 128];

struct Params {
    const float* x;        // [B, 96]
    const float* u;        // [B, 32]
    const float* mixf;     // [1]
    const float* P;        // [4]
    const float* W[2][3];
    const float* Bb[2][3];
    const float* W4[2];    // [64]
    const float* b4[2];    // [1]
    const float* tW[2][3]; // [4, O, 128]
    const float* tb[2][3]; // [4, O]
    float*       out;      // [2*B]
};

__device__ __forceinline__ float to_tf32(float x) {
    asm("cvt.rna.tf32.f32 %0, %0;" : "+f"(x));
    return x;
}
__device__ __forceinline__ uint32_t s2u(const void* p) {
    uint32_t a;
    asm("{ .reg .u64 t; cvta.to.shared.u64 t, %1; cvt.u32.u64 %0, t; }"
        : "=r"(a) : "l"(p));
    return a;
}
__device__ __forceinline__ void ldsm4(uint32_t* r, uint32_t addr) {
    asm volatile("ldmatrix.sync.aligned.m8n8.x4.shared.b16 {%0,%1,%2,%3}, [%4];"
                 : "=r"(r[0]), "=r"(r[1]), "=r"(r[2]), "=r"(r[3]) : "r"(addr));
}
__device__ __forceinline__ void mma8(float* c, const uint32_t* a,
                                     uint32_t b0, uint32_t b1) {
    asm volatile(
        "mma.sync.aligned.m16n8k8.row.col.f32.tf32.tf32.f32 "
        "{%0,%1,%2,%3}, {%4,%5,%6,%7}, {%8,%9}, {%0,%1,%2,%3};"
        : "+f"(c[0]), "+f"(c[1]), "+f"(c[2]), "+f"(c[3])
        : "r"(a[0]), "r"(a[1]), "r"(a[2]), "r"(a[3]), "r"(b0), "r"(b1));
}
__device__ __forceinline__ void cpasync16(uint32_t dst, const void* src) {
    asm volatile("cp.async.cg.shared.global [%0], [%1], 16;"
                 :: "r"(dst), "l"(src) : "memory");
}

// ---------------- preprocessing kernel ----------------
__global__ void prep_kernel(Params p) {
    const int idx = blockIdx.x * 256 + threadIdx.x;
    if (idx < 30 * 4096) {                      // weight float4s
        const int img = idx >> 12;
        const int rem = idx & 4095;
        const int n   = rem >> 5;               // output row 0..127
        const int q   = rem & 31;               // float4 within row
        const int h = img / 15, rr = img % 15, L = rr / 5, s = rr % 5;
        const int O = (L == 2) ? 64 : 128;
        float4 v = make_float4(0.f, 0.f, 0.f, 0.f);
        if (n < O) {
            const float* W = (s == 4) ? p.W[h][L]
                                      : p.tW[h][L] + (size_t)s * O * 128;
            v = *reinterpret_cast<const float4*>(W + (size_t)n * 128 + q * 4);
            v.x = to_tf32(v.x); v.y = to_tf32(v.y);
            v.z = to_tf32(v.z); v.w = to_tf32(v.w);
        }
        const int off = SWF(n, q * 4);          // 16B-aligned (swizzle bits 2..4)
        *reinterpret_cast<float4*>(g_wimg + (size_t)img * 16384 + off) = v;
    } else if (idx < 30 * 4096 + 960) {         // bias float4s
        const int b   = idx - 30 * 4096;
        const int img = b >> 5;
        const int q   = b & 31;
        const int h = img / 15, rr = img % 15, L = rr / 5, s = rr % 5;
        const int O = (L == 2) ? 64 : 128;
        const float* B = (s == 4) ? p.Bb[h][L] : p.tb[h][L] + s * O;
        const int o = q * 4;
        float4 v;
        v.x = (o + 0 < O) ? B[o + 0] : 0.f;
        v.y = (o + 1 < O) ? B[o + 1] : 0.f;
        v.z = (o + 2 < O) ? B[o + 2] : 0.f;
        v.w = (o + 3 < O) ? B[o + 3] : 0.f;
        *reinterpret_cast<float4*>(g_bimg + img * 128 + o) = v;
    }
}

// ---------------- main kernel ----------------
// slot: which 512B bias slot this image's bias lands in (double-buffered).
__device__ __forceinline__ void prefetch_img(uint32_t wbuf_u, uint32_t bias_u,
                                             int img, int slot, int tid) {
    const float4* wsrc = reinterpret_cast<const float4*>(g_wimg + (size_t)img * 16384);
    #pragma unroll
    for (int i = 0; i < 16; i++)
        cpasync16(wbuf_u + (uint32_t)(tid + i * 256) * 16, wsrc + tid + i * 256);
    if (tid < 32)
        cpasync16(bias_u + (uint32_t)slot * 512 + tid * 16,
                  reinterpret_cast<const float4*>(g_bimg + img * 128) + tid);
    asm volatile("cp.async.commit_group;" ::: "memory");
}

__global__ void __launch_bounds__(THREADS)
critic_main(Params p) {
    extern __shared__ float smem[];
    const uint32_t sbase  = s2u(smem);
    const uint32_t wbuf_u = sbase + WBUF_OFF;
    const uint32_t bias_u = sbase + BIAS_OFF;

    const int tid  = threadIdx.x;
    const int lane = tid & 31;
    const int wid  = tid >> 5;
    const int wm   = wid & 1;          // 2 warps over m (batch)
    const int wn   = wid >> 1;         // 4 warps over n (outputs)
    const int mbase = wm * 32;
    const int nbase = wn * 32;
    const int lq = lane >> 2, lr = lane & 3;
    const int r8 = lane & 7, sel = lane >> 3;
    const int row0 = blockIdx.x * BM;

    // ldmatrix per-thread address components (32-bit-element x4 pattern)
    const int rowA0 = mbase + ((sel & 1) << 3) + r8;      // mt=0 (rows +0/+8)
    const int rowA1 = rowA0 + 16;                          // mt=1
    const int rowB0 = nbase + ((sel >> 1) << 3) + r8;      // nt pair {0,1}
    const int rowB1 = rowB0 + 16;                          // nt pair {2,3}
    const uint32_t mA = ((((sel >> 1) << 2) ^ (r8 << 2)) << 2);  // byte XOR mask
    const uint32_t mB = ((((sel & 1) << 2) ^ (r8 << 2)) << 2);
    const uint32_t aoff0 = (uint32_t)rowA0 * 512;
    const uint32_t aoff1 = (uint32_t)rowA1 * 512;
    const uint32_t boff0 = wbuf_u + (uint32_t)rowB0 * 512;
    const uint32_t boff1 = wbuf_u + (uint32_t)rowB1 * 512;

    const float m = __ldg(p.mixf);
    const float inv_m = 1.0f - m;
    float Pk[4];
    #pragma unroll
    for (int k = 0; k < 4; k++) Pk[k] = __ldg(p.P + k);

    for (int h = 0; h < 2; h++) {
        prefetch_img(wbuf_u, bias_u, h * 15, 0, tid);   // t=0 -> slot 0

        // ---- load xu tile -> act buffer 4 (swizzled, tf32-rounded) ----
        {
            float* dst = smem + 4 * (ACT_B / 4);
            #pragma unroll 2
            for (int i = tid; i < 64 * 32; i += THREADS) {
                const int r = i >> 5;
                const int q = i & 31;
                float4 v;
                if (q < 24)
                    v = *reinterpret_cast<const float4*>(
                        p.x + (size_t)(row0 + r) * 96 + q * 4);
                else
                    v = *reinterpret_cast<const float4*>(
                        p.u + (size_t)(row0 + r) * 32 + (q - 24) * 4);
                v.x = to_tf32(v.x); v.y = to_tf32(v.y);
                v.z = to_tf32(v.z); v.w = to_tf32(v.w);
                *reinterpret_cast<float4*>(dst + SWF(r, q * 4)) = v;
            }
        }

        float mix[2][4][4];
        for (int t = 0; t < 15; t++) {
            const int L = t / 5, s = t % 5;
            const bool is_main = (s == 4);
            if (s == 0) {
                #pragma unroll
                for (int mt = 0; mt < 2; mt++)
                    #pragma unroll
                    for (int nt = 0; nt < 4; nt++)
                        #pragma unroll
                        for (int c = 0; c < 4; c++) mix[mt][nt][c] = 0.f;
            }

            asm volatile("cp.async.wait_group 0;" ::: "memory");
            __syncthreads();    // weights+bias in, prev epilogue visible

            // ---- k-loop: [64,128] x [128,128]^T tf32 ----
            const int inb = (L == 0) ? 4 : (is_main ? 4 : s);
            const uint32_t abase0 = sbase + (uint32_t)inb * ACT_B + aoff0;
            const uint32_t abase1 = sbase + (uint32_t)inb * ACT_B + aoff1;

            float acc[2][4][4];
            #pragma unroll
            for (int mt = 0; mt < 2; mt++)
                #pragma unroll
                for (int nt = 0; nt < 4; nt++)
                    #pragma unroll
                    for (int c = 0; c < 4; c++) acc[mt][nt][c] = 0.f;

            #pragma unroll
            for (int j = 0; j < 16; j++) {
                const uint32_t kb = (uint32_t)(j * 32);   // k0*4 bytes
                uint32_t a0[4], a1[4], b0[4], b1[4];
                const uint32_t offA = kb ^ mA;
                const uint32_t offB = kb ^ mB;
                ldsm4(a0, abase0 + offA);
                ldsm4(a1, abase1 + offA);
                ldsm4(b0, boff0 + offB);
                ldsm4(b1, boff1 + offB);
                mma8(acc[0][0], a0, b0[0], b0[1]);
                mma8(acc[0][1], a0, b0[2], b0[3]);
                mma8(acc[0][2], a0, b1[0], b1[1]);
                mma8(acc[0][3], a0, b1[2], b1[3]);
                mma8(acc[1][0], a1, b0[0], b0[1]);
                mma8(acc[1][1], a1, b0[2], b0[3]);
                mma8(acc[1][2], a1, b1[0], b1[1]);
                mma8(acc[1][3], a1, b1[2], b1[3]);
            }

            __syncthreads();    // all reads of wbuf + act done

            // prefetch next stream: weights -> wbuf (safe: reads done),
            // bias -> OTHER slot (safe: this stream reads slot t&1)
            if (t < 14)
                prefetch_img(wbuf_u, bias_u, h * 15 + t + 1, (t + 1) & 1, tid);

            // ---- epilogue: bias + mix + relu + swizzled STS ----
            const float sc = is_main ? inv_m : (m * Pk[s]);
            const int bslot = BIAS_F + (t & 1) * 128;
            float bias[4][2];
            #pragma unroll
            for (int nt = 0; nt < 4; nt++) {
                bias[nt][0] = smem[bslot + nbase + nt * 8 + lr * 2 + 0];
                bias[nt][1] = smem[bslot + nbase + nt * 8 + lr * 2 + 1];
            }
            float* outb = smem + (is_main ? 4 : s) * (ACT_B / 4);
            #pragma unroll
            for (int mt = 0; mt < 2; mt++)
                #pragma unroll
                for (int nt = 0; nt < 4; nt++)
                    #pragma unroll
                    for (int c = 0; c < 4; c++) {
                        const float val = acc[mt][nt][c] + bias[nt][c & 1];
                        float ov;
                        if (!is_main) {
                            mix[mt][nt][c] = fmaf(sc, val, mix[mt][nt][c]);
                            ov = val;
                        } else {
                            ov = fmaf(sc, val, mix[mt][nt][c]);
                        }
                        const int row = mbase + mt * 16 + lq + ((c >> 1) << 3);
                        const int col = nbase + nt * 8 + lr * 2 + (c & 1);
                        outb[SWF(row, col)] = to_tf32(fmaxf(ov, 0.f));
                    }
        }

        __syncthreads();
        // ---- final layer: out = h3 . W4 + b4 ----
        if (tid < 64) {
            float sum = __ldg(p.b4[h]);
            const float* W4 = p.W4[h];
            const float* hb = smem + 4 * (ACT_B / 4);
            #pragma unroll
            for (int j = 0; j < 64; j++)
                sum = fmaf(hb[SWF(tid, j)], __ldg(W4 + j), sum);
            p.out[(size_t)h * BATCH + row0 + tid] = sum;
        }
        __syncthreads();   // act4 free before head-1 xu reload
    }
}

extern "C" void kernel_launch(void* const* d_in, const int* in_sizes, int n_in,
                              void* d_out, int out_size) {
    (void)in_sizes; (void)n_in; (void)out_size;
    Params p;
    p.x    = (const float*)d_in[0];
    p.u    = (const float*)d_in[1];
    p.mixf = (const float*)d_in[2];
    p.P    = (const float*)d_in[3];
    for (int h = 0; h < 2; h++) {
        const int base = 4 + h * 8;
        p.W[h][0]  = (const float*)d_in[base + 0];
        p.Bb[h][0] = (const float*)d_in[base + 1];
        p.W[h][1]  = (const float*)d_in[base + 2];
        p.Bb[h][1] = (const float*)d_in[base + 3];
        p.W[h][2]  = (const float*)d_in[base + 4];
        p.Bb[h][2] = (const float*)d_in[base + 5];
        p.W4[h]    = (const float*)d_in[base + 6];
        p.b4[h]    = (const float*)d_in[base + 7];
        const int tbase = 20 + h * 6;
        p.tW[h][0] = (const float*)d_in[tbase + 0];
        p.tb[h][0] = (const float*)d_in[tbase + 1];
        p.tW[h][1] = (const float*)d_in[tbase + 2];
        p.tb[h][1] = (const float*)d_in[tbase + 3];
        p.tW[h][2] = (const float*)d_in[tbase + 4];
        p.tb[h][2] = (const float*)d_in[tbase + 5];
    }
    p.out = (float*)d_out;

    prep_kernel<<<(30 * 4096 + 960 + 255) / 256, 256>>>(p);
    cudaFuncSetAttribute(critic_main,
                         cudaFuncAttributeMaxDynamicSharedMemorySize, SMEM_BYTES);
    critic_main<<<NBLK, THREADS, SMEM_BYTES>>>(p);
}

// round 5
// speedup vs baseline: 1.6337x; 1.1133x over previous
#include <cuda_runtime.h>
#include <cstdint>
#include <cstddef>

// ---------------------------------------------------------------------------
// Critic_Mix fused kernel (round 4): mma.sync tf32 + ldmatrix.x4 + cp.async
// weight images. R4: L=2 padded-half skip (warps wn>=2 idle, 32KB weight
// fetch) + 2-stage register-pipelined k-loop + launch_bounds(256,1).
// ---------------------------------------------------------------------------

#define THREADS   256
#define BM        64
#define BATCH     262144
#define NBLK      (BATCH / BM)

#define ACT_B      32768
#define WBUF_OFF   (5 * ACT_B)          // 163840
#define BIAS_OFF   (WBUF_OFF + 65536)   // 229376
#define SMEM_BYTES (BIAS_OFF + 1024)    // 230400 <= 232448
#define BIAS_F     (BIAS_OFF / 4)

#define SWF(row, k) (((row) * 128) + ((k) ^ (((row) & 7) << 2)))

__device__ float g_wimg[30 * 16384];
__device__ float g_bimg[30 * 128];

struct Params {
    const float* x;
    const float* u;
    const float* mixf;
    const float* P;
    const float* W[2][3];
    const float* Bb[2][3];
    const float* W4[2];
    const float* b4[2];
    const float* tW[2][3];
    const float* tb[2][3];
    float*       out;
};

__device__ __forceinline__ float to_tf32(float x) {
    asm("cvt.rna.tf32.f32 %0, %0;" : "+f"(x));
    return x;
}
__device__ __forceinline__ uint32_t s2u(const void* p) {
    uint32_t a;
    asm("{ .reg .u64 t; cvta.to.shared.u64 t, %1; cvt.u32.u64 %0, t; }"
        : "=r"(a) : "l"(p));
    return a;
}
__device__ __forceinline__ void ldsm4(uint32_t* r, uint32_t addr) {
    asm volatile("ldmatrix.sync.aligned.m8n8.x4.shared.b16 {%0,%1,%2,%3}, [%4];"
                 : "=r"(r[0]), "=r"(r[1]), "=r"(r[2]), "=r"(r[3]) : "r"(addr));
}
__device__ __forceinline__ void mma8(float* c, const uint32_t* a,
                                     uint32_t b0, uint32_t b1) {
    asm volatile(
        "mma.sync.aligned.m16n8k8.row.col.f32.tf32.tf32.f32 "
        "{%0,%1,%2,%3}, {%4,%5,%6,%7}, {%8,%9}, {%0,%1,%2,%3};"
        : "+f"(c[0]), "+f"(c[1]), "+f"(c[2]), "+f"(c[3])
        : "r"(a[0]), "r"(a[1]), "r"(a[2]), "r"(a[3]), "r"(b0), "r"(b1));
}
__device__ __forceinline__ void cpasync16(uint32_t dst, const void* src) {
    asm volatile("cp.async.cg.shared.global [%0], [%1], 16;"
                 :: "r"(dst), "l"(src) : "memory");
}

// ---------------- preprocessing kernel ----------------
__global__ void prep_kernel(Params p) {
    const int idx = blockIdx.x * 256 + threadIdx.x;
    if (idx < 30 * 4096) {
        const int img = idx >> 12;
        const int rem = idx & 4095;
        const int n   = rem >> 5;
        const int q   = rem & 31;
        const int h = img / 15, rr = img % 15, L = rr / 5, s = rr % 5;
        const int O = (L == 2) ? 64 : 128;
        float4 v = make_float4(0.f, 0.f, 0.f, 0.f);
        if (n < O) {
            const float* W = (s == 4) ? p.W[h][L]
                                      : p.tW[h][L] + (size_t)s * O * 128;
            v = *reinterpret_cast<const float4*>(W + (size_t)n * 128 + q * 4);
            v.x = to_tf32(v.x); v.y = to_tf32(v.y);
            v.z = to_tf32(v.z); v.w = to_tf32(v.w);
        }
        const int off = SWF(n, q * 4);
        *reinterpret_cast<float4*>(g_wimg + (size_t)img * 16384 + off) = v;
    } else if (idx < 30 * 4096 + 960) {
        const int b   = idx - 30 * 4096;
        const int img = b >> 5;
        const int q   = b & 31;
        const int h = img / 15, rr = img % 15, L = rr / 5, s = rr % 5;
        const int O = (L == 2) ? 64 : 128;
        const float* B = (s == 4) ? p.Bb[h][L] : p.tb[h][L] + s * O;
        const int o = q * 4;
        float4 v;
        v.x = (o + 0 < O) ? B[o + 0] : 0.f;
        v.y = (o + 1 < O) ? B[o + 1] : 0.f;
        v.z = (o + 2 < O) ? B[o + 2] : 0.f;
        v.w = (o + 3 < O) ? B[o + 3] : 0.f;
        *reinterpret_cast<float4*>(g_bimg + img * 128 + o) = v;
    }
}

// ---------------- main kernel ----------------
// nv: number of 4KB chunks of weight image to fetch (16 full, 8 for L=2)
__device__ __forceinline__ void prefetch_img(uint32_t wbuf_u, uint32_t bias_u,
                                             int img, int slot, int nv, int tid) {
    const float4* wsrc = reinterpret_cast<const float4*>(g_wimg + (size_t)img * 16384);
    #pragma unroll
    for (int i = 0; i < 16; i++)
        if (i < nv)
            cpasync16(wbuf_u + (uint32_t)(tid + i * 256) * 16, wsrc + tid + i * 256);
    if (tid < 32)
        cpasync16(bias_u + (uint32_t)slot * 512 + tid * 16,
                  reinterpret_cast<const float4*>(g_bimg + img * 128) + tid);
    asm volatile("cp.async.commit_group;" ::: "memory");
}

__global__ void __launch_bounds__(THREADS, 1)
critic_main(Params p) {
    extern __shared__ float smem[];
    const uint32_t sbase  = s2u(smem);
    const uint32_t wbuf_u = sbase + WBUF_OFF;
    const uint32_t bias_u = sbase + BIAS_OFF;

    const int tid  = threadIdx.x;
    const int lane = tid & 31;
    const int wid  = tid >> 5;
    const int wm   = wid & 1;
    const int wn   = wid >> 1;
    const int mbase = wm * 32;
    const int nbase = wn * 32;
    const int lq = lane >> 2, lr = lane & 3;
    const int r8 = lane & 7, sel = lane >> 3;
    const int row0 = blockIdx.x * BM;
    const bool lowN = (wn < 2);     // outputs 0..63 (valid at O=64 layers)

    const int rowA0 = mbase + ((sel & 1) << 3) + r8;
    const int rowA1 = rowA0 + 16;
    const int rowB0 = nbase + ((sel >> 1) << 3) + r8;
    const int rowB1 = rowB0 + 16;
    const uint32_t mA = ((((sel >> 1) << 2) ^ (r8 << 2)) << 2);
    const uint32_t mB = ((((sel & 1) << 2) ^ (r8 << 2)) << 2);
    const uint32_t aoff0 = (uint32_t)rowA0 * 512;
    const uint32_t aoff1 = (uint32_t)rowA1 * 512;
    const uint32_t boff0 = wbuf_u + (uint32_t)rowB0 * 512;
    const uint32_t boff1 = wbuf_u + (uint32_t)rowB1 * 512;

    const float m = __ldg(p.mixf);
    const float inv_m = 1.0f - m;
    float Pk[4];
    #pragma unroll
    for (int k = 0; k < 4; k++) Pk[k] = __ldg(p.P + k);

    for (int h = 0; h < 2; h++) {
        prefetch_img(wbuf_u, bias_u, h * 15, 0, 16, tid);

        // ---- xu -> act buffer 4 ----
        {
            float* dst = smem + 4 * (ACT_B / 4);
            #pragma unroll 2
            for (int i = tid; i < 64 * 32; i += THREADS) {
                const int r = i >> 5;
                const int q = i & 31;
                float4 v;
                if (q < 24)
                    v = *reinterpret_cast<const float4*>(
                        p.x + (size_t)(row0 + r) * 96 + q * 4);
                else
                    v = *reinterpret_cast<const float4*>(
                        p.u + (size_t)(row0 + r) * 32 + (q - 24) * 4);
                v.x = to_tf32(v.x); v.y = to_tf32(v.y);
                v.z = to_tf32(v.z); v.w = to_tf32(v.w);
                *reinterpret_cast<float4*>(dst + SWF(r, q * 4)) = v;
            }
        }

        float mix[2][4][4];
        for (int t = 0; t < 15; t++) {
            const int L = t / 5, s = t % 5;
            const bool is_main = (s == 4);
            const bool active  = (L < 2) || lowN;   // L=2: wn>=2 = padding only
            if (s == 0) {
                #pragma unroll
                for (int mt = 0; mt < 2; mt++)
                    #pragma unroll
                    for (int nt = 0; nt < 4; nt++)
                        #pragma unroll
                        for (int c = 0; c < 4; c++) mix[mt][nt][c] = 0.f;
            }

            asm volatile("cp.async.wait_group 0;" ::: "memory");
            __syncthreads();

            float acc[2][4][4];
            #pragma unroll
            for (int mt = 0; mt < 2; mt++)
                #pragma unroll
                for (int nt = 0; nt < 4; nt++)
                    #pragma unroll
                    for (int c = 0; c < 4; c++) acc[mt][nt][c] = 0.f;

            if (active) {
                const int inb = (L == 0) ? 4 : (is_main ? 4 : s);
                const uint32_t abase0 = sbase + (uint32_t)inb * ACT_B + aoff0;
                const uint32_t abase1 = sbase + (uint32_t)inb * ACT_B + aoff1;

                // 2-stage register-pipelined k-loop
                uint32_t fa0[2][4], fa1[2][4], fb0[2][4], fb1[2][4];
                {
                    const uint32_t offA = 0 ^ mA, offB = 0 ^ mB;
                    ldsm4(fa0[0], abase0 + offA);
                    ldsm4(fa1[0], abase1 + offA);
                    ldsm4(fb0[0], boff0 + offB);
                    ldsm4(fb1[0], boff1 + offB);
                }
                #pragma unroll
                for (int j = 0; j < 16; j++) {
                    const int cur = j & 1, nxt = cur ^ 1;
                    if (j < 15) {
                        const uint32_t kb = (uint32_t)((j + 1) * 32);
                        const uint32_t offA = kb ^ mA, offB = kb ^ mB;
                        ldsm4(fa0[nxt], abase0 + offA);
                        ldsm4(fa1[nxt], abase1 + offA);
                        ldsm4(fb0[nxt], boff0 + offB);
                        ldsm4(fb1[nxt], boff1 + offB);
                    }
                    mma8(acc[0][0], fa0[cur], fb0[cur][0], fb0[cur][1]);
                    mma8(acc[0][1], fa0[cur], fb0[cur][2], fb0[cur][3]);
                    mma8(acc[0][2], fa0[cur], fb1[cur][0], fb1[cur][1]);
                    mma8(acc[0][3], fa0[cur], fb1[cur][2], fb1[cur][3]);
                    mma8(acc[1][0], fa1[cur], fb0[cur][0], fb0[cur][1]);
                    mma8(acc[1][1], fa1[cur], fb0[cur][2], fb0[cur][3]);
                    mma8(acc[1][2], fa1[cur], fb1[cur][0], fb1[cur][1]);
                    mma8(acc[1][3], fa1[cur], fb1[cur][2], fb1[cur][3]);
                }
            }

            __syncthreads();    // all wbuf/act reads done

            if (t < 14) {
                const int nL = (t + 1) / 5;
                prefetch_img(wbuf_u, bias_u, h * 15 + t + 1, (t + 1) & 1,
                             (nL == 2) ? 8 : 16, tid);
            }

            if (active) {
                const float sc = is_main ? inv_m : (m * Pk[s]);
                const int bslot = BIAS_F + (t & 1) * 128;
                float bias[4][2];
                #pragma unroll
                for (int nt = 0; nt < 4; nt++) {
                    bias[nt][0] = smem[bslot + nbase + nt * 8 + lr * 2 + 0];
                    bias[nt][1] = smem[bslot + nbase + nt * 8 + lr * 2 + 1];
                }
                const bool do_store = is_main || (L < 2);
                float* outb = smem + (is_main ? 4 : s) * (ACT_B / 4);
                #pragma unroll
                for (int mt = 0; mt < 2; mt++)
                    #pragma unroll
                    for (int nt = 0; nt < 4; nt++)
                        #pragma unroll
                        for (int c = 0; c < 4; c++) {
                            const float val = acc[mt][nt][c] + bias[nt][c & 1];
                            float ov;
                            if (!is_main) {
                                mix[mt][nt][c] = fmaf(sc, val, mix[mt][nt][c]);
                                ov = val;
                            } else {
                                ov = fmaf(sc, val, mix[mt][nt][c]);
                            }
                            if (do_store) {
                                const int row = mbase + mt * 16 + lq + ((c >> 1) << 3);
                                const int col = nbase + nt * 8 + lr * 2 + (c & 1);
                                outb[SWF(row, col)] = to_tf32(fmaxf(ov, 0.f));
                            }
                        }
            }
        }

        __syncthreads();
        // ---- final layer ----
        if (tid < 64) {
            float sum = __ldg(p.b4[h]);
            const float* W4 = p.W4[h];
            const float* hb = smem + 4 * (ACT_B / 4);
            #pragma unroll
            for (int j = 0; j < 64; j++)
                sum = fmaf(hb[SWF(tid, j)], __ldg(W4 + j), sum);
            p.out[(size_t)h * BATCH + row0 + tid] = sum;
        }
        __syncthreads();
    }
}

extern "C" void kernel_launch(void* const* d_in, const int* in_sizes, int n_in,
                              void* d_out, int out_size) {
    (void)in_sizes; (void)n_in; (void)out_size;
    Params p;
    p.x    = (const float*)d_in[0];
    p.u    = (const float*)d_in[1];
    p.mixf = (const float*)d_in[2];
    p.P    = (const float*)d_in[3];
    for (int h = 0; h < 2; h++) {
        const int base = 4 + h * 8;
        p.W[h][0]  = (const float*)d_in[base + 0];
        p.Bb[h][0] = (const float*)d_in[base + 1];
        p.W[h][1]  = (const float*)d_in[base + 2];
        p.Bb[h][1] = (const float*)d_in[base + 3];
        p.W[h][2]  = (const float*)d_in[base + 4];
        p.Bb[h][2] = (const float*)d_in[base + 5];
        p.W4[h]    = (const float*)d_in[base + 6];
        p.b4[h]    = (const float*)d_in[base + 7];
        const int tbase = 20 + h * 6;
        p.tW[h][0] = (const float*)d_in[tbase + 0];
        p.tb[h][0] = (const float*)d_in[tbase + 1];
        p.tW[h][1] = (const float*)d_in[tbase + 2];
        p.tb[h][1] = (const float*)d_in[tbase + 3];
        p.tW[h][2] = (const float*)d_in[tbase + 4];
        p.tb[h][2] = (const float*)d_in[tbase + 5];
    }
    p.out = (float*)d_out;

    prep_kernel<<<(30 * 4096 + 960 + 255) / 256, 256>>>(p);
    cudaFuncSetAttribute(critic_main,
                         cudaFuncAttributeMaxDynamicSharedMemorySize, SMEM_BYTES);
    critic_main<<<NBLK, THREADS, SMEM_BYTES>>>(p);
}